// round 16
// baseline (speedup 1.0000x reference)
#include <cuda_runtime.h>
#include <cuda_bf16.h>
#include <math.h>
#include <stdint.h>

// Problem shape
#define NB 32
#define CD 512
#define TD 2048
#define KC 512
#define QL 6
#define TT 128

#define ELEMS    33554432ULL
#define IDX_OFF  33554432ULL
#define SCAL_OFF 33947648ULL

// GEMM smem geometry: per stage, 4 swizzled panels of 128 rows x 32 bf16 (64B)
#define STRIDE   64
#define OFF_A_H  0
#define OFF_A_L  8192
#define OFF_B_H  16384
#define OFF_B_L  24576
#define STG      32768
#define NST      3
#define DYN_BYTES (NST * STG)                 // 98304 B, 2 CTAs/SM (192KB)

// Device scratch (allocation-free rule)
__device__ float         g_res  [NB * CD * TD];
__device__ float         g_quant[NB * CD * TD];
__device__ __nv_bfloat16 g_xh   [NB * TD * CD];   // residual bf16 hi, [n][t][c]
__device__ __nv_bfloat16 g_xl   [NB * TD * CD];   // residual bf16 lo
__device__ __nv_bfloat16 g_cbh  [QL * KC * CD];
__device__ __nv_bfloat16 g_cbl  [QL * KC * CD];
__device__ float         g_cbT  [QL * CD * KC];   // fp32 codebook transposed [q][c][k]
__device__ float         g_cbn2f[QL * KC];
__device__ float         g_S1   [NB * TD];        // per-token ||res||^2 (exact chain)
__device__ int           g_code [NB * TD];        // per-token selected code
__device__ unsigned int  g_hist [QL * KC];
__device__ double        g_lossPart[QL * 512];

// ---- helpers -------------------------------------------------------------
__device__ __forceinline__ void cpa16(unsigned dst, const void* src) {
    asm volatile("cp.async.cg.shared.global [%0], [%1], 16;" :: "r"(dst), "l"(src));
}
__device__ __forceinline__ void cp_commit() { asm volatile("cp.async.commit_group;"); }

// bf16 HMMA m16n8k16 (plain sm_80+ PTX — NOT arch-"a" gated, unlike tcgen05)
__device__ __forceinline__ void mma_bf16(float* d, const uint32_t* a,
                                         uint32_t b0, uint32_t b1) {
    asm volatile(
        "mma.sync.aligned.m16n8k16.row.col.f32.bf16.bf16.f32 "
        "{%0,%1,%2,%3},{%4,%5,%6,%7},{%8,%9},{%0,%1,%2,%3};"
        : "+f"(d[0]), "+f"(d[1]), "+f"(d[2]), "+f"(d[3])
        : "r"(a[0]), "r"(a[1]), "r"(a[2]), "r"(a[3]), "r"(b0), "r"(b1));
}

// ldmatrix x4 (sm_75+)
__device__ __forceinline__ void ldsm4(uint32_t* r, unsigned a) {
    asm volatile("ldmatrix.sync.aligned.m8n8.x4.shared.b16 {%0,%1,%2,%3}, [%4];"
                 : "=r"(r[0]), "=r"(r[1]), "=r"(r[2]), "=r"(r[3]) : "r"(a));
}

__device__ __forceinline__ void merge2(float v, int k,
                                       float& D1, int& K1, float& D2, int& K2) {
    if (v < D1 || (v == D1 && k < K1)) { D2 = D1; K2 = K1; D1 = v; K1 = k; }
    else if (v < D2 || (v == D2 && k < K2)) { D2 = v; K2 = k; }
}

// swizzle: 16B segment s at row r lives at segment s ^ ((r>>1)&3)
__device__ __forceinline__ unsigned swz_off(unsigned row, unsigned seg) {
    return row * STRIDE + ((seg ^ ((row >> 1) & 3u)) << 4);
}

// ---- prep: hist zero, sequential-fp32 codebook norms, bf16 hi/lo split ----
__global__ void vq_prep(const float* cb) {
    int gid = blockIdx.x * 256 + threadIdx.x;
    if (gid < QL * KC) {
        g_hist[gid] = 0u;
        const float* row = cb + (size_t)gid * CD;
        __nv_bfloat16* ph = g_cbh + (size_t)gid * CD;
        __nv_bfloat16* pl = g_cbl + (size_t)gid * CD;
        float s = 0.0f;
        for (int c = 0; c < CD; c++) {
            float v = row[c];
            s = __fadd_rn(s, __fmul_rn(v, v));
            __nv_bfloat16 h = __float2bfloat16(v);
            ph[c] = h;
            pl[c] = __float2bfloat16(v - __bfloat162float(h));
        }
        g_cbn2f[gid] = s;
    }
}

// ---- coalesced codebook transpose: g_cbT[q][c][k] = cb[q][k][c] ----
__global__ void vq_tr(const float* cb) {
    __shared__ float tile[32][33];
    int q  = blockIdx.z;
    int k0 = blockIdx.x * 32, c0 = blockIdx.y * 32;
    const float* src = cb + (size_t)q * KC * CD;
    for (int i = threadIdx.y; i < 32; i += 8)
        tile[i][threadIdx.x] = src[(size_t)(k0 + i) * CD + c0 + threadIdx.x];
    __syncthreads();
    float* dst = g_cbT + (size_t)q * CD * KC;
    for (int i = threadIdx.y; i < 32; i += 8)
        dst[(size_t)(c0 + i) * KC + k0 + threadIdx.x] = tile[threadIdx.x][i];
}

// ---- layer-0 A split + S1: x -> g_xh/g_xl ([n][t][c]), g_S1 (exact chain) ----
__global__ void vq_convx(const float* x) {
    int n = blockIdx.y, t = blockIdx.x * 128 + threadIdx.x;
    const float* p = x + (size_t)n * CD * TD + t;
    size_t ao = ((size_t)n * TD + t) * CD;
    float s1 = 0.0f;
    for (int g = 0; g < 64; g++) {
        unsigned hw[4], lw[4];
#pragma unroll
        for (int e2 = 0; e2 < 4; e2++) {
            float v0 = p[(size_t)(g * 8 + e2 * 2) * TD];
            float v1 = p[(size_t)(g * 8 + e2 * 2 + 1) * TD];
            s1 = __fadd_rn(s1, __fmul_rn(v0, v0));   // c ascending
            s1 = __fadd_rn(s1, __fmul_rn(v1, v1));
            __nv_bfloat16 h0 = __float2bfloat16(v0), h1 = __float2bfloat16(v1);
            __nv_bfloat16 l0 = __float2bfloat16(v0 - __bfloat162float(h0));
            __nv_bfloat16 l1 = __float2bfloat16(v1 - __bfloat162float(h1));
            hw[e2] = (unsigned)__bfloat16_as_ushort(h0) | ((unsigned)__bfloat16_as_ushort(h1) << 16);
            lw[e2] = (unsigned)__bfloat16_as_ushort(l0) | ((unsigned)__bfloat16_as_ushort(l1) << 16);
        }
        *(uint4*)(g_xh + ao + g * 8) = make_uint4(hw[0], hw[1], hw[2], hw[3]);
        *(uint4*)(g_xl + ao + g * 8) = make_uint4(lw[0], lw[1], lw[2], lw[3]);
    }
    g_S1[(size_t)n * TD + t] = s1;
}

// ---- assign kernel: pipelined HMMA GEMM + top-2 + rescan + indices ----
__global__ void __launch_bounds__(256, 2) vq_assign(
    const float* x, const float* cb, float* out, int q)
{
    extern __shared__ char dyn[];
    __shared__ float  sS1[TT];
    __shared__ int    sK[TT];
    __shared__ int    sList[TT];
    __shared__ int    sCnt;
    __shared__ float  sRd[256];
    __shared__ int    sRk[256];

    const int tid  = threadIdx.x;
    const int lane = tid & 31;
    const int warp = tid >> 5;
    const int gid  = lane >> 2;
    const int tig  = lane & 3;
    const int tg   = warp & 3;
    const int kg   = warp >> 2;
    const int n    = blockIdx.y;
    const int t0   = blockIdx.x * TT;
    const float* resin = (q == 0) ? x : g_res;
    const float* cbnF  = g_cbn2f + q * KC;
    const float* cbT   = g_cbT + (size_t)q * CD * KC;
    const __nv_bfloat16* cbhq = g_cbh + (size_t)q * KC * CD;
    const __nv_bfloat16* cblq = g_cbl + (size_t)q * KC * CD;
    const size_t base  = (size_t)n * CD * TD;
    const size_t abase = ((size_t)n * TD + t0) * CD;
    const unsigned sb  = (unsigned)__cvta_generic_to_shared(dyn);
    if (tid == 0) sCnt = 0;
    if (tid < TT) sS1[tid] = g_S1[(size_t)n * TD + t0 + tid];

    auto pf = [&](int s) {
        int kt = s >> 4, cc = s & 15;
        int c0 = cc * 32, k0 = kt * 128;
        unsigned so = sb + (unsigned)((s % NST) * STG);
#pragma unroll
        for (int m = 0; m < 4; m++) {
            int idx = m * 256 + tid;
            int hl  = idx >> 9;
            unsigned row = (unsigned)((idx >> 2) & 127);
            unsigned seg = (unsigned)(idx & 3);
            unsigned sw  = swz_off(row, seg);
            cpa16(so + (hl ? OFF_A_L : OFF_A_H) + sw,
                  (hl ? g_xl : g_xh) + abase + (size_t)row * CD + c0 + seg * 8);
            cpa16(so + (hl ? OFF_B_L : OFF_B_H) + sw,
                  (hl ? cblq : cbhq) + (size_t)(k0 + row) * CD + c0 + seg * 8);
        }
        cp_commit();
    };

    pf(0); pf(1);

    float bd1[4], bd2[4]; int bk1[4], bk2[4];
#pragma unroll
    for (int sl = 0; sl < 4; sl++) {
        bd1[sl] = __int_as_float(0x7f800000); bd2[sl] = bd1[sl];
        bk1[sl] = 0; bk2[sl] = 0;
    }
    float d[2][8][4];
#pragma unroll
    for (int mt = 0; mt < 2; mt++)
#pragma unroll
        for (int nt = 0; nt < 8; nt++)
#pragma unroll
            for (int r = 0; r < 4; r++) d[mt][nt][r] = 0.0f;

    // per-lane fragment rows (swizzle handled per-access; depends only on row)
    const unsigned aRowL = (unsigned)(lane & 15);
    const unsigned aSegL = (unsigned)(lane >> 4);          // +0 / +16B column seg
    const unsigned bRowL = (unsigned)(lane & 7);
    const unsigned bSegL = (unsigned)((lane >> 3) & 1);
    const unsigned bNtl  = (unsigned)(lane >> 4);

    // rows are loop-invariant per mt / per j: precompute row and its swizzle key
    unsigned aRow[2], aKey[2];
#pragma unroll
    for (int mt = 0; mt < 2; mt++) {
        aRow[mt] = (unsigned)(tg * 32 + mt * 16) + aRowL;
        aKey[mt] = (aRow[mt] >> 1) & 3u;
    }
    unsigned bRow[4], bKey[4];
#pragma unroll
    for (int j = 0; j < 4; j++) {
        bRow[j] = (unsigned)(kg * 64) + (2u * j + bNtl) * 8u + bRowL;
        bKey[j] = (bRow[j] >> 1) & 3u;
    }

    // ---- HMMA mainloop: 64 steps, 3-stage ring, ONE sync per step ----
    for (int s = 0; s < 64; s++) {
        asm volatile("cp.async.wait_group 1;");
        __syncthreads();                       // all warps done with stage (s-1)%3
        if (s + 2 < 64) pf(s + 2); else cp_commit();
        const unsigned bufo = sb + (unsigned)((s % NST) * STG);

#pragma unroll
        for (int csi = 0; csi < 2; csi++) {
            uint32_t ah[2][4], al[2][4];
#pragma unroll
            for (int mt = 0; mt < 2; mt++) {
                unsigned g  = (unsigned)(csi * 2) + aSegL;
                unsigned ra = bufo + OFF_A_H + aRow[mt] * STRIDE + ((g ^ aKey[mt]) << 4);
                ldsm4(ah[mt], ra);
                ldsm4(al[mt], ra + (OFF_A_L - OFF_A_H));
            }
            uint32_t bh[8][2], bl[8][2];
#pragma unroll
            for (int j = 0; j < 4; j++) {
                unsigned g  = (unsigned)(csi * 2) + bSegL;
                unsigned rb = bufo + OFF_B_H + bRow[j] * STRIDE + ((g ^ bKey[j]) << 4);
                uint32_t r4[4];
                ldsm4(r4, rb);
                bh[2*j][0] = r4[0]; bh[2*j][1] = r4[1];
                bh[2*j+1][0] = r4[2]; bh[2*j+1][1] = r4[3];
                ldsm4(r4, rb + (OFF_B_L - OFF_B_H));
                bl[2*j][0] = r4[0]; bl[2*j][1] = r4[1];
                bl[2*j+1][0] = r4[2]; bl[2*j+1][1] = r4[3];
            }
#pragma unroll
            for (int p = 0; p < 3; p++)
#pragma unroll
                for (int nt = 0; nt < 8; nt++)
#pragma unroll
                    for (int mt = 0; mt < 2; mt++) {
                        const uint32_t* A = (p == 2) ? al[mt] : ah[mt];
                        uint32_t B0 = (p == 1) ? bl[nt][0] : bh[nt][0];
                        uint32_t B1 = (p == 1) ? bl[nt][1] : bh[nt][1];
                        mma_bf16(d[mt][nt], A, B0, B1);
                        // ll dropped: |sum al*bl| ~2e-5 << tau, rescue covers it
                    }
        }

        if ((s & 15) == 15) {
            int kt = s >> 4;
#pragma unroll
            for (int mt = 0; mt < 2; mt++)
#pragma unroll
                for (int h = 0; h < 2; h++) {
                    int slot = mt * 2 + h;
                    int tok  = tg * 32 + mt * 16 + h * 8 + gid;
                    float s1v = sS1[tok];
#pragma unroll
                    for (int nt = 0; nt < 8; nt++)
#pragma unroll
                        for (int e = 0; e < 2; e++) {
                            int k = kt * 128 + kg * 64 + nt * 8 + tig * 2 + e;
                            float da = __fmaf_rn(-2.0f, d[mt][nt][h * 2 + e], cbnF[k]) + s1v;
                            merge2(da, k, bd1[slot], bk1[slot], bd2[slot], bk2[slot]);
                            d[mt][nt][h * 2 + e] = 0.0f;
                        }
                }
        }
    }
    asm volatile("cp.async.wait_group 0;");
    __syncthreads();

    // ---- cross-thread top-2 reduce ----
    float* eD1 = (float*)dyn;
    float* eD2 = (float*)(dyn + 4096);
    int*   eK1 = (int*)(dyn + 8192);
    int*   eK2 = (int*)(dyn + 12288);
    {
        int g = tig * 2 + kg;
#pragma unroll
        for (int mt = 0; mt < 2; mt++)
#pragma unroll
            for (int h = 0; h < 2; h++) {
                int slot = mt * 2 + h;
                int tok  = tg * 32 + mt * 16 + h * 8 + gid;
                eD1[g * TT + tok] = bd1[slot]; eK1[g * TT + tok] = bk1[slot];
                eD2[g * TT + tok] = bd2[slot]; eK2[g * TT + tok] = bk2[slot];
            }
    }
    __syncthreads();
    if (tid < TT) {
        float D1 = __int_as_float(0x7f800000), D2 = D1;
        int K1 = 0, K2 = 0;
#pragma unroll
        for (int g = 0; g < 8; g++) {
            merge2(eD1[g * TT + tid], eK1[g * TT + tid], D1, K1, D2, K2);
            merge2(eD2[g * TT + tid], eK2[g * TT + tid], D1, K1, D2, K2);
        }
        sK[tid] = K1;
        float tau = 2e-6f * (sS1[tid] + 512.0f) + 4e-5f;
        if (D2 - D1 < tau) {
            int slot = atomicAdd(&sCnt, 1);
            sList[slot] = tid;
        }
    }
    __syncthreads();

    // ---- exact rescan of flagged tokens (reference fp32 chain, coalesced) ----
    {
        int cnt = sCnt;
        for (int e = 0; e < cnt; e++) {
            int tl = sList[e];
            const float* xp = resin + base + t0 + tl;
            float a0 = 0.0f, a1 = 0.0f;
            for (int c = 0; c < CD; c++) {
                float xv = xp[(size_t)c * TD];
                const float* row = cbT + (size_t)c * KC;
                a0 = __fmaf_rn(row[tid],       xv, a0);
                a1 = __fmaf_rn(row[tid + 256], xv, a1);
            }
            float S = sS1[tl];
            float d0 = __fadd_rn(__fsub_rn(S, __fmul_rn(2.0f, a0)), cbnF[tid]);
            float d1 = __fadd_rn(__fsub_rn(S, __fmul_rn(2.0f, a1)), cbnF[tid + 256]);
            float bdv = d0; int bkv = tid;
            if (d1 < bdv) { bdv = d1; bkv = tid + 256; }
            sRd[tid] = bdv; sRk[tid] = bkv;
            __syncthreads();
            for (int off = 128; off > 0; off >>= 1) {
                if (tid < off) {
                    float od = sRd[tid + off]; int ok = sRk[tid + off];
                    if (od < sRd[tid] || (od == sRd[tid] && ok < sRk[tid])) {
                        sRd[tid] = od; sRk[tid] = ok;
                    }
                }
                __syncthreads();
            }
            if (tid == 0) sK[tl] = sRk[0];
            __syncthreads();
        }
    }

    // ---- indices + histogram + code handoff ----
    if (tid < TT) {
        int K = sK[tid];
        g_code[(size_t)n * TD + t0 + tid] = K;
        out[IDX_OFF + ((size_t)(n * TD + t0 + tid)) * QL + q] = (float)K;
        atomicAdd(&g_hist[q * KC + K], 1u);
    }
}

// ---- apply kernel (high occupancy): gather + update + split + S1(next) ----
__global__ void __launch_bounds__(256, 5) vq_apply(
    const float* x, const float* cb, float* out, int q)
{
    __shared__ float  cbS[TT * 65];
    __shared__ int    sK[TT];
    __shared__ double sL[8];

    const int tid  = threadIdx.x;
    const int lane = tid & 31;
    const int warp = tid >> 5;
    const int n    = blockIdx.y;
    const int t0   = blockIdx.x * TT;
    const float* resin = (q == 0) ? x : g_res;
    const float* cbq   = cb + (size_t)q * KC * CD;
    const size_t base  = (size_t)n * CD * TD;
    const size_t abase = ((size_t)n * TD + t0) * CD;

    if (tid < TT) sK[tid] = g_code[(size_t)n * TD + t0 + tid];
    __syncthreads();

    const int tl   = tid & 127;
    const int half = tid >> 7;
    double lacc = 0.0;
    for (int ch = 0; ch < 8; ch++) {
        const int c0 = ch * 64;
        if (ch) __syncthreads();                // protect cbS reuse
#pragma unroll
        for (int u = 0; u < 16; u++) {
            int tt = warp * 16 + u;
            const float* cr = cbq + (size_t)sK[tt] * CD + c0;
            cbS[tt * 65 + lane]      = cr[lane];
            cbS[tt * 65 + lane + 32] = cr[lane + 32];
        }
        __syncthreads();
#pragma unroll
        for (int gph = 0; gph < 4; gph++) {
            unsigned hw[4] = {0, 0, 0, 0}, lw[4] = {0, 0, 0, 0};
            int cb0 = c0 + half * 32 + gph * 8;
#pragma unroll
            for (int e = 0; e < 8; e++) {
                int c = cb0 + e;
                size_t off = base + (size_t)c * TD + t0 + tl;
                float xf = resin[off];
                float xd = cbS[tl * 65 + (c - c0)];
                float qv = __fadd_rn(xf, __fsub_rn(xd, xf));   // straight-through
                float df = __fsub_rn(xf, xd);
                lacc += (double)__fmul_rn(df, df);
                float qa = (q == 0) ? qv : __fadd_rn(g_quant[off], qv);
                if (q < QL - 1) {
                    float rn = __fsub_rn(xf, qv);
                    g_res[off]   = rn;
                    g_quant[off] = qa;
                    __nv_bfloat16 h = __float2bfloat16(rn);
                    __nv_bfloat16 l = __float2bfloat16(rn - __bfloat162float(h));
                    hw[e >> 1] |= (unsigned)__bfloat16_as_ushort(h) << ((e & 1) * 16);
                    lw[e >> 1] |= (unsigned)__bfloat16_as_ushort(l) << ((e & 1) * 16);
                } else {
                    out[off] = qa;
                }
            }
            if (q < QL - 1) {
                size_t ao = abase + (size_t)tl * CD + cb0;
                *(uint4*)(g_xh + ao) = make_uint4(hw[0], hw[1], hw[2], hw[3]);
                *(uint4*)(g_xl + ao) = make_uint4(lw[0], lw[1], lw[2], lw[3]);
            }
        }
    }

    // ---- deterministic block loss partial ----
    for (int o = 16; o > 0; o >>= 1) lacc += __shfl_down_sync(0xffffffffu, lacc, o);
    if (lane == 0) sL[warp] = lacc;
    __syncthreads();
    if (tid == 0) {
        double s = 0.0;
        for (int w = 0; w < 8; w++) s += sL[w];
        g_lossPart[q * 512 + blockIdx.y * 16 + blockIdx.x] = s;
    }

    // ---- S1 for next layer: strict sequential fp32 chain over new residual ----
    if (q < QL - 1 && tid < TT) {
        const float* p = g_res + base + t0 + tid;   // block-local writes, post-barrier
        float s = 0.0f;
        for (int c = 0; c < CD; c++) {
            float v = p[(size_t)c * TD];
            s = __fadd_rn(s, __fmul_rn(v, v));
        }
        g_S1[(size_t)n * TD + t0 + tid] = s;
    }
}

// ---- scalars: commit loss mean + perplexity ----
__global__ void vq_final(float* out) {
    __shared__ double sPerp[QL], sLoss[QL];
    int warp = threadIdx.x >> 5, lane = threadIdx.x & 31;
    if (warp < QL) {
        int q = warp;
        double ls = 0.0;
        for (int b = lane; b < 512; b += 32) ls += g_lossPart[q * 512 + b];
        double ent = 0.0;
        for (int k = lane; k < KC; k += 32) {
            float cnt  = (float)g_hist[q * KC + k];
            float prob = cnt / 65536.0f;
            ent += (double)prob * log((double)prob + 1e-7);
        }
        for (int o = 16; o > 0; o >>= 1) {
            ls  += __shfl_down_sync(0xffffffffu, ls, o);
            ent += __shfl_down_sync(0xffffffffu, ent, o);
        }
        if (lane == 0) { sLoss[q] = ls / (double)ELEMS; sPerp[q] = exp(-ent); }
    }
    __syncthreads();
    if (threadIdx.x == 0) {
        double lsum = 0.0, psum = 0.0;
        for (int q = 0; q < QL; q++) { lsum += sLoss[q]; psum += sPerp[q]; }
        out[SCAL_OFF]     = (float)(lsum / (double)QL);
        out[SCAL_OFF + 1] = (float)(psum / (double)QL);
    }
}

extern "C" void kernel_launch(void* const* d_in, const int* in_sizes, int n_in,
                              void* d_out, int out_size) {
    const float* x  = (const float*)d_in[0];   // [32, 512, 2048] f32
    const float* cb = (const float*)d_in[1];   // [6, 512, 512]  f32
    float* out = (float*)d_out;

    cudaFuncSetAttribute(vq_assign,
                         cudaFuncAttributeMaxDynamicSharedMemorySize, DYN_BYTES);

    vq_prep<<<12, 256>>>(cb);
    vq_tr<<<dim3(16, 16, QL), dim3(32, 8)>>>(cb);
    vq_convx<<<dim3(16, 32), 128>>>(x);
    dim3 grid(TD / TT, NB);                    // (16, 32) = 512 blocks
    for (int q = 0; q < QL; q++) {
        vq_assign<<<grid, 256, DYN_BYTES>>>(x, cb, out, q);
        vq_apply <<<grid, 256>>>(x, cb, out, q);
    }
    vq_final<<<1, QL * 32>>>(out);
}